// round 2
// baseline (speedup 1.0000x reference)
#include <cuda_runtime.h>
#include <cstdint>
#include <cstddef>

#define N_SAMPLES 1024
#define IN_F      512
#define OUT_F     512
#define N_HEADS   32
#define N_SPLITS  4
#define N_COMBOS  (N_HEADS * N_SPLITS)

// ---------------------------------------------------------------------------
// Device scratch (no cudaMalloc allowed anywhere)
// ---------------------------------------------------------------------------
__device__ int g_sorted[N_SAMPLES];      // sample ids sorted by combo
__device__ int g_cstart[N_COMBOS + 1];   // combo -> range in g_sorted

// ---------------------------------------------------------------------------
// Grouping kernel: counting sort of samples by combo = head*4 + split.
// One block, 256 threads. Order within a group is nondeterministic (shared
// atomics) but every sample's result is computed identically regardless of
// its slot, so the output is deterministic.
// ---------------------------------------------------------------------------
__global__ void setup_groups_kernel(const int* __restrict__ head_ix,
                                    const int* __restrict__ split_ix) {
    __shared__ int cnt[N_COMBOS];
    __shared__ int off[N_COMBOS + 1];
    __shared__ int cur[N_COMBOS];
    const int t = threadIdx.x;

    if (t < N_COMBOS) cnt[t] = 0;
    __syncthreads();

    for (int i = t; i < N_SAMPLES; i += blockDim.x)
        atomicAdd(&cnt[head_ix[i] * N_SPLITS + split_ix[i]], 1);
    __syncthreads();

    if (t == 0) {
        int s = 0;
        for (int c = 0; c < N_COMBOS; ++c) { off[c] = s; s += cnt[c]; }
        off[N_COMBOS] = s;
    }
    __syncthreads();

    if (t <= N_COMBOS) g_cstart[t] = off[t];
    if (t < N_COMBOS)  cur[t] = off[t];
    __syncthreads();

    for (int i = t; i < N_SAMPLES; i += blockDim.x) {
        int c = head_ix[i] * N_SPLITS + split_ix[i];
        g_sorted[atomicAdd(&cur[c], 1)] = i;
    }
}

// ---------------------------------------------------------------------------
// Packed-pair fp32x2 FMA (SASS FFMA2 — only reachable via PTX fma.rn.f32x2)
// ---------------------------------------------------------------------------
#define FMA2(d, a, b, c) \
    asm("fma.rn.f32x2 %0, %1, %2, %3;" : "=l"(d) : "l"(a), "l"(b), "l"(c))

// ---------------------------------------------------------------------------
// Grouped GEMV kernel.
//   Grid: (numGroups, OUT_F/256 col tiles, CHUNK_SLOTS row-chunk slots)
//   Block: 256 threads, thread t owns one output column c = tile*256 + t.
//   R_TILE rows per chunk, packed as R_TILE/2 row-pairs so each smem LDS.128
//   yields two b64 (row0,row1) operands for FFMA2 with no repacking.
//   IS_DELTA=false: out = x@W + bias (writes). IS_DELTA=true: out += 0.1*x@DW.
//   Disjoint (sample, column) ownership per block -> no atomics needed.
// ---------------------------------------------------------------------------
template <int R_TILE, bool IS_DELTA>
__global__ void __launch_bounds__(256)
group_mm_kernel(const float* __restrict__ X,
                const float* __restrict__ W,
                const float* __restrict__ bias,
                float* __restrict__ out) {
    constexpr int R_PAIRS = R_TILE / 2;

    const int g = blockIdx.x;   // head (base) or combo (delta)
    int start, end, head;
    if (IS_DELTA) {
        start = g_cstart[g];
        end   = g_cstart[g + 1];
        head  = g >> 2;               // unused for delta epilogue
    } else {
        start = g_cstart[g * N_SPLITS];
        end   = g_cstart[(g + 1) * N_SPLITS];
        head  = g;
    }
    if (start >= end) return;

    const int t = threadIdx.x;
    const int c = blockIdx.y * 256 + t;
    const int slots = gridDim.z;

    // Weight column pointer for this thread: W[g][k][c], stride OUT_F per k.
    const float* __restrict__ Wc = W + (size_t)g * (IN_F * OUT_F) + c;

    // x_s layout: pair rp, k -> { X[s(2rp)][k], X[s(2rp+1)][k] } interleaved.
    __shared__ float x_s[R_PAIRS * 2 * IN_F];
    __shared__ int   s_idx[R_TILE];

    for (int r0 = start + blockIdx.z * R_TILE; r0 < end; r0 += slots * R_TILE) {
        if (t < R_TILE) s_idx[t] = (r0 + t < end) ? g_sorted[r0 + t] : -1;
        __syncthreads();

        // Cooperative fill of packed x tile (coalesced global reads).
        for (int idx = t; idx < R_TILE * IN_F; idx += 256) {
            int r = idx >> 9;            // idx / IN_F
            int k = idx & (IN_F - 1);
            int s = s_idx[r];
            float v = (s >= 0) ? X[s * IN_F + k] : 0.0f;
            x_s[(r >> 1) * (2 * IN_F) + k * 2 + (r & 1)] = v;
        }
        __syncthreads();

        unsigned long long acc[R_PAIRS];
#pragma unroll
        for (int rp = 0; rp < R_PAIRS; ++rp) acc[rp] = 0ull;

#pragma unroll 4
        for (int k = 0; k < IN_F; k += 2) {
            float wa = Wc[(size_t)k * OUT_F];
            float wb = Wc[(size_t)(k + 1) * OUT_F];
            unsigned long long wa2, wb2;
            asm("mov.b64 %0, {%1, %1};" : "=l"(wa2) : "f"(wa));
            asm("mov.b64 %0, {%1, %1};" : "=l"(wb2) : "f"(wb));
#pragma unroll
            for (int rp = 0; rp < R_PAIRS; ++rp) {
                // LDS.128 broadcast: (x[r0,k], x[r1,k], x[r0,k+1], x[r1,k+1])
                const ulonglong2 xv = *reinterpret_cast<const ulonglong2*>(
                    &x_s[rp * (2 * IN_F) + 2 * k]);
                FMA2(acc[rp], xv.x, wa2, acc[rp]);
                FMA2(acc[rp], xv.y, wb2, acc[rp]);
            }
        }

        const float bv = IS_DELTA ? 0.0f : bias[head * OUT_F + c];
#pragma unroll
        for (int rp = 0; rp < R_PAIRS; ++rp) {
            float lo, hi;
            asm("mov.b64 {%0, %1}, %2;" : "=f"(lo), "=f"(hi) : "l"(acc[rp]));
            const int s0 = s_idx[2 * rp];
            const int s1 = s_idx[2 * rp + 1];
            if (IS_DELTA) {
                if (s0 >= 0) out[s0 * OUT_F + c] += 0.1f * lo;
                if (s1 >= 0) out[s1 * OUT_F + c] += 0.1f * hi;
            } else {
                if (s0 >= 0) out[s0 * OUT_F + c] = lo + bv;
                if (s1 >= 0) out[s1 * OUT_F + c] = hi + bv;
            }
        }
        __syncthreads();   // protect x_s before next chunk iteration
    }
}

// ---------------------------------------------------------------------------
// kernel_launch: inputs in metadata order
//   0 input        f32 [1024, 512]
//   1 head_ix      i32 [1024]
//   2 split_ix     i32 [1024]
//   3 weight       f32 [32, 512, 512]
//   4 delta_weight f32 [128, 512, 512]
//   5 bias         f32 [32, 512]
// The uniquely-sized tensors are additionally resolved by element count for
// robustness; head_ix/split_ix (both 1024) rely on metadata order.
// ---------------------------------------------------------------------------
extern "C" void kernel_launch(void* const* d_in, const int* in_sizes, int n_in,
                              void* d_out, int out_size) {
    const float* X    = (const float*)d_in[0];
    const int*   hix  = (const int*)d_in[1];
    const int*   six  = (const int*)d_in[2];
    const float* W    = (const float*)d_in[3];
    const float* DW   = (const float*)d_in[4];
    const float* bias = (const float*)d_in[5];

    // Defensive size-based resolution for uniquely-sized inputs.
    for (int i = 0; i < n_in; ++i) {
        switch (in_sizes[i]) {
            case N_SAMPLES * IN_F:            X    = (const float*)d_in[i]; break;
            case N_HEADS * IN_F * OUT_F:      W    = (const float*)d_in[i]; break;
            case N_COMBOS * IN_F * OUT_F:     DW   = (const float*)d_in[i]; break;
            case N_HEADS * OUT_F:             bias = (const float*)d_in[i]; break;
            default: break; // head_ix / split_ix stay at metadata positions
        }
    }

    float* out = (float*)d_out;

    setup_groups_kernel<<<1, 256>>>(hix, six);

    // Base: 32 heads x 2 col tiles x 4 chunk slots (16 rows each; internal
    // loop covers pathological head counts > 64).
    group_mm_kernel<16, false><<<dim3(N_HEADS, OUT_F / 256, 4), 256>>>(X, W, bias, out);

    // Delta: 128 combos x 2 col tiles x 2 chunk slots (8 rows each).
    group_mm_kernel<8, true><<<dim3(N_COMBOS, OUT_F / 256, 2), 256>>>(X, DW, bias, out);
}

// round 5
// speedup vs baseline: 1.1530x; 1.1530x over previous
#include <cuda_runtime.h>
#include <cstdint>
#include <cstddef>

#define N_SAMPLES 1024
#define IN_F      512
#define OUT_F     512
#define N_HEADS   32
#define N_SPLITS  4
#define N_COMBOS  (N_HEADS * N_SPLITS)
#define COL_TILE  128
#define DELTA_SCALE 0.1f

// ---------------------------------------------------------------------------
// Device scratch (no cudaMalloc allowed anywhere)
// ---------------------------------------------------------------------------
__device__ int g_sorted[N_SAMPLES];      // sample ids sorted by combo
__device__ int g_cstart[N_COMBOS + 1];   // combo -> range in g_sorted

// ---------------------------------------------------------------------------
// Grouping kernel: counting sort by combo = head*4 + split.
// One block, 256 threads, parallel Hillis-Steele scan (was serial on t0).
// ---------------------------------------------------------------------------
__global__ void setup_groups_kernel(const int* __restrict__ head_ix,
                                    const int* __restrict__ split_ix) {
    __shared__ int cnt[N_COMBOS];
    __shared__ int scan[N_COMBOS];
    __shared__ int cur[N_COMBOS];
    const int t = threadIdx.x;

    if (t < N_COMBOS) cnt[t] = 0;
    __syncthreads();

    for (int i = t; i < N_SAMPLES; i += blockDim.x)
        atomicAdd(&cnt[head_ix[i] * N_SPLITS + split_ix[i]], 1);
    __syncthreads();

    if (t < N_COMBOS) scan[t] = cnt[t];
    __syncthreads();
    // inclusive scan over 128 entries
    for (int d = 1; d < N_COMBOS; d <<= 1) {
        int v = 0;
        if (t < N_COMBOS && t >= d) v = scan[t - d];
        __syncthreads();
        if (t < N_COMBOS) scan[t] += v;
        __syncthreads();
    }

    if (t == 0) g_cstart[0] = 0;
    if (t < N_COMBOS) {
        g_cstart[t + 1] = scan[t];
        cur[t] = scan[t] - cnt[t];   // exclusive start
    }
    __syncthreads();

    for (int i = t; i < N_SAMPLES; i += blockDim.x) {
        int c = head_ix[i] * N_SPLITS + split_ix[i];
        g_sorted[atomicAdd(&cur[c], 1)] = i;
    }
}

// ---------------------------------------------------------------------------
// Packed-pair fp32x2 FMA (SASS FFMA2 — only reachable via PTX fma.rn.f32x2)
// ---------------------------------------------------------------------------
#define FMA2(d, a, b, c) \
    asm("fma.rn.f32x2 %0, %1, %2, %3;" : "=l"(d) : "l"(a), "l"(b), "l"(c))

// ---------------------------------------------------------------------------
// Core per-chunk compute: thread owns column c; accumulates R_PAIRS row-pairs
// over k=0..511 with explicit double-buffered W prefetch (MLP = 8 LDGs in
// flight while FMAs of the previous batch execute).
// x_s layout: pair rp, k -> { x[row 2rp][k], x[row 2rp+1][k] } interleaved,
// so one LDS.128 broadcast yields two packed b64 FFMA2 operands.
// ---------------------------------------------------------------------------
template <int R_PAIRS, bool IS_DELTA>
__device__ __forceinline__ void compute_rows(const float* __restrict__ Wc,
                                             const float* x_s,
                                             const int*   s_idx,
                                             float bv,
                                             float* __restrict__ out,
                                             int c) {
    unsigned long long acc[R_PAIRS];
#pragma unroll
    for (int rp = 0; rp < R_PAIRS; ++rp) acc[rp] = 0ull;

    float wbuf[2][8];
#pragma unroll
    for (int j = 0; j < 8; ++j) wbuf[0][j] = Wc[(size_t)j * OUT_F];

#pragma unroll 2
    for (int kb = 0; kb < IN_F; kb += 8) {
        const int cur = (kb >> 3) & 1;
        const int nxt = cur ^ 1;
        const int kp  = (kb + 8) & (IN_F - 1);   // wraps on last iter (harmless L1 hit)
#pragma unroll
        for (int j = 0; j < 8; ++j)
            wbuf[nxt][j] = Wc[(size_t)(kp + j) * OUT_F];

#pragma unroll
        for (int j = 0; j < 8; j += 2) {
            unsigned long long wa2, wb2;
            asm("mov.b64 %0, {%1, %1};" : "=l"(wa2) : "f"(wbuf[cur][j]));
            asm("mov.b64 %0, {%1, %1};" : "=l"(wb2) : "f"(wbuf[cur][j + 1]));
#pragma unroll
            for (int rp = 0; rp < R_PAIRS; ++rp) {
                const ulonglong2 xv = *reinterpret_cast<const ulonglong2*>(
                    &x_s[rp * (2 * IN_F) + 2 * (kb + j)]);
                FMA2(acc[rp], xv.x, wa2, acc[rp]);
                FMA2(acc[rp], xv.y, wb2, acc[rp]);
            }
        }
    }

#pragma unroll
    for (int rp = 0; rp < R_PAIRS; ++rp) {
        float lo, hi;
        asm("mov.b64 {%0, %1}, %2;" : "=f"(lo), "=f"(hi) : "l"(acc[rp]));
        const int s0 = s_idx[2 * rp];
        const int s1 = s_idx[2 * rp + 1];
        if (IS_DELTA) {
            if (s0 >= 0) out[s0 * OUT_F + c] += DELTA_SCALE * lo;
            if (s1 >= 0) out[s1 * OUT_F + c] += DELTA_SCALE * hi;
        } else {
            if (s0 >= 0) out[s0 * OUT_F + c] = lo + bv;
            if (s1 >= 0) out[s1 * OUT_F + c] = hi + bv;
        }
    }
}

// ---------------------------------------------------------------------------
// Grouped GEMV kernel.
//   Grid: (numGroups, OUT_F/128 col tiles, slots). Block: 128 threads,
//   thread t owns column c = tile*128 + t. R_TILE=16 rows per chunk; chunks
//   with <=8 live rows dispatch a half-size compute to skip padded FMAs.
//   IS_DELTA=false: out = x@W + bias. IS_DELTA=true: out += 0.1*(x@DW).
// ---------------------------------------------------------------------------
template <bool IS_DELTA>
__global__ void __launch_bounds__(COL_TILE)
group_mm_kernel(const float* __restrict__ X,
                const float* __restrict__ W,
                const float* __restrict__ bias,
                float* __restrict__ out) {
    constexpr int R_TILE  = 16;
    constexpr int R_PAIRS = R_TILE / 2;

    const int g = blockIdx.x;   // head (base) or combo (delta)
    int start, end;
    if (IS_DELTA) {
        start = g_cstart[g];
        end   = g_cstart[g + 1];
    } else {
        start = g_cstart[g * N_SPLITS];
        end   = g_cstart[(g + 1) * N_SPLITS];
    }
    if (start >= end) return;

    const int t = threadIdx.x;
    const int c = blockIdx.y * COL_TILE + t;
    const int stride = gridDim.z * R_TILE;

    const float* __restrict__ Wc = W + (size_t)g * (IN_F * OUT_F) + c;
    const float bv = IS_DELTA ? 0.0f : bias[g * OUT_F + c];

    __shared__ float x_s[R_PAIRS * 2 * IN_F];   // 32 KB
    __shared__ int   s_idx[R_TILE];

    for (int r0 = start + blockIdx.z * R_TILE; r0 < end; r0 += stride) {
        const int rows = min(R_TILE, end - r0);
        if (t < R_TILE) s_idx[t] = (t < rows) ? g_sorted[r0 + t] : -1;
        __syncthreads();

        const bool small = (rows <= R_TILE / 2);
        const int fill = (small ? R_PAIRS / 2 : R_PAIRS) * 2 * IN_F;

        for (int idx = t; idx < fill; idx += COL_TILE) {
            const int r = idx >> 9;            // idx / IN_F
            const int k = idx & (IN_F - 1);
            const int s = s_idx[r];
            x_s[(r >> 1) * (2 * IN_F) + 2 * k + (r & 1)] =
                (s >= 0) ? X[s * IN_F + k] : 0.0f;
        }
        __syncthreads();

        if (small)
            compute_rows<R_PAIRS / 2, IS_DELTA>(Wc, x_s, s_idx, bv, out, c);
        else
            compute_rows<R_PAIRS, IS_DELTA>(Wc, x_s, s_idx, bv, out, c);
        __syncthreads();   // protect x_s / s_idx before next chunk
    }
}

// ---------------------------------------------------------------------------
// kernel_launch: inputs in metadata order
//   0 input f32[1024,512]  1 head_ix i32[1024]  2 split_ix i32[1024]
//   3 weight f32[32,512,512]  4 delta_weight f32[128,512,512]  5 bias f32[32,512]
// ---------------------------------------------------------------------------
extern "C" void kernel_launch(void* const* d_in, const int* in_sizes, int n_in,
                              void* d_out, int out_size) {
    const float* X    = (const float*)d_in[0];
    const int*   hix  = (const int*)d_in[1];
    const int*   six  = (const int*)d_in[2];
    const float* W    = (const float*)d_in[3];
    const float* DW   = (const float*)d_in[4];
    const float* bias = (const float*)d_in[5];

    // Defensive size-based resolution for uniquely-sized inputs.
    for (int i = 0; i < n_in; ++i) {
        switch (in_sizes[i]) {
            case N_SAMPLES * IN_F:        X    = (const float*)d_in[i]; break;
            case N_HEADS * IN_F * OUT_F:  W    = (const float*)d_in[i]; break;
            case N_COMBOS * IN_F * OUT_F: DW   = (const float*)d_in[i]; break;
            case N_HEADS * OUT_F:         bias = (const float*)d_in[i]; break;
            default: break; // head_ix / split_ix keep metadata positions
        }
    }

    float* out = (float*)d_out;

    setup_groups_kernel<<<1, 256>>>(hix, six);

    // Base: 32 heads x 4 col tiles x 3 chunk slots (16 rows each; internal
    // loop covers heads with > 48 rows).
    group_mm_kernel<false><<<dim3(N_HEADS, OUT_F / COL_TILE, 3), COL_TILE>>>(X, W, bias, out);

    // Delta: 128 combos x 4 col tiles x 1 slot (internal loop covers > 16 rows).
    group_mm_kernel<true><<<dim3(N_COMBOS, OUT_F / COL_TILE, 1), COL_TILE>>>(X, DW, bias, out);
}

// round 8
// speedup vs baseline: 1.7216x; 1.4931x over previous
#include <cuda_runtime.h>
#include <cstdint>
#include <cstddef>

#define N_SAMPLES 1024
#define IN_F      512
#define OUT_F     512
#define N_HEADS   32
#define N_SPLITS  4
#define N_COMBOS  (N_HEADS * N_SPLITS)
#define DELTA_SCALE 0.1f

// ---------------------------------------------------------------------------
// Device scratch (no cudaMalloc allowed anywhere)
// ---------------------------------------------------------------------------
__device__ int g_sorted[N_SAMPLES];      // sample ids grouped by combo
__device__ int g_cstart[N_COMBOS + 1];   // combo -> range in g_sorted

// ---------------------------------------------------------------------------
// Grouping kernel: counting sort by combo = head*4 + split.
// One block, 1024 threads (1 sample/thread), warp-shuffle scan.
// ---------------------------------------------------------------------------
__global__ void __launch_bounds__(N_SAMPLES)
setup_groups_kernel(const int* __restrict__ head_ix,
                    const int* __restrict__ split_ix) {
    __shared__ int cnt[N_COMBOS];
    __shared__ int cur[N_COMBOS];
    const int t = threadIdx.x;

    if (t < N_COMBOS) cnt[t] = 0;
    __syncthreads();

    const int my_c = head_ix[t] * N_SPLITS + split_ix[t];
    atomicAdd(&cnt[my_c], 1);
    __syncthreads();

    if (t < 32) {
        // lane L owns combos 4L..4L+3
        int c0 = cnt[4 * t + 0], c1 = cnt[4 * t + 1];
        int c2 = cnt[4 * t + 2], c3 = cnt[4 * t + 3];
        int v = c0 + c1 + c2 + c3;
        // inclusive shuffle scan over 32 lanes
        int s = v;
#pragma unroll
        for (int d = 1; d < 32; d <<= 1) {
            int u = __shfl_up_sync(0xFFFFFFFFu, s, d);
            if (t >= d) s += u;
        }
        int run = s - v;                       // exclusive prefix
        if (t == 0) g_cstart[0] = 0;
        run += c0; g_cstart[4 * t + 1] = run; cur[4 * t + 0] = run - c0;
        run += c1; g_cstart[4 * t + 2] = run; cur[4 * t + 1] = run - c1;
        run += c2; g_cstart[4 * t + 3] = run; cur[4 * t + 2] = run - c2;
        run += c3; g_cstart[4 * t + 4] = run; cur[4 * t + 3] = run - c3;
    }
    __syncthreads();

    g_sorted[atomicAdd(&cur[my_c], 1)] = t;
}

// ---------------------------------------------------------------------------
// Packed-pair fp32x2 FMA (SASS FFMA2 — only reachable via PTX fma.rn.f32x2)
// ---------------------------------------------------------------------------
#define FMA2(d, a, b, c) \
    asm("fma.rn.f32x2 %0, %1, %2, %3;" : "=l"(d) : "l"(a), "l"(b), "l"(c))
#define PACK2(d, s) \
    asm("mov.b64 %0, {%1, %1};" : "=l"(d) : "f"(s))

// ---------------------------------------------------------------------------
// Core compute: thread owns 2 adjacent columns (c, c+1); accumulates R_PAIRS
// row-pairs over k=0..511. W and DW columns are streamed as float2 with a
// one-batch-ahead register prefetch; weights combined on the fly:
//   w' = W + 0.1*DW  (1 scalar FFMA per element, shared by all row-pairs).
// x_s layout: pair rp, k -> { x[row 2rp][k], x[row 2rp+1][k] } interleaved,
// so one LDS.128 yields packed b64 operands for two consecutive k.
// ---------------------------------------------------------------------------
template <int R_PAIRS>
__device__ __forceinline__ void compute_rows(const float* __restrict__ Wc,
                                             const float* __restrict__ Dc,
                                             const float* x_s,
                                             const int*   s_idx,
                                             float2 bv,
                                             float* __restrict__ out,
                                             int c) {
    unsigned long long acc0[R_PAIRS], acc1[R_PAIRS];   // col c / col c+1
#pragma unroll
    for (int rp = 0; rp < R_PAIRS; ++rp) { acc0[rp] = 0ull; acc1[rp] = 0ull; }

    float2 wb[2][8], db[2][8];
#pragma unroll
    for (int j = 0; j < 8; ++j) {
        wb[0][j] = *reinterpret_cast<const float2*>(Wc + (size_t)j * OUT_F);
        db[0][j] = *reinterpret_cast<const float2*>(Dc + (size_t)j * OUT_F);
    }

#pragma unroll 2
    for (int kb = 0; kb < IN_F; kb += 8) {
        const int cur = (kb >> 3) & 1;
        const int nxt = cur ^ 1;
        const int kp  = (kb + 8) & (IN_F - 1);   // wraps last iter (L1 hit, unused)
#pragma unroll
        for (int j = 0; j < 8; ++j) {
            wb[nxt][j] = *reinterpret_cast<const float2*>(Wc + (size_t)(kp + j) * OUT_F);
            db[nxt][j] = *reinterpret_cast<const float2*>(Dc + (size_t)(kp + j) * OUT_F);
        }

#pragma unroll
        for (int j = 0; j < 8; j += 2) {        // k-pair (kb+j, kb+j+1)
            const float wa0 = fmaf(DELTA_SCALE, db[cur][j].x,     wb[cur][j].x);
            const float wa1 = fmaf(DELTA_SCALE, db[cur][j].y,     wb[cur][j].y);
            const float wb0 = fmaf(DELTA_SCALE, db[cur][j + 1].x, wb[cur][j + 1].x);
            const float wb1 = fmaf(DELTA_SCALE, db[cur][j + 1].y, wb[cur][j + 1].y);
            unsigned long long a0, a1, b0, b1;
            PACK2(a0, wa0); PACK2(a1, wa1); PACK2(b0, wb0); PACK2(b1, wb1);
#pragma unroll
            for (int rp = 0; rp < R_PAIRS; ++rp) {
                const ulonglong2 xv = *reinterpret_cast<const ulonglong2*>(
                    &x_s[rp * (2 * IN_F) + 2 * (kb + j)]);
                FMA2(acc0[rp], xv.x, a0, acc0[rp]);   // col c,   k
                FMA2(acc1[rp], xv.x, a1, acc1[rp]);   // col c+1, k
                FMA2(acc0[rp], xv.y, b0, acc0[rp]);   // col c,   k+1
                FMA2(acc1[rp], xv.y, b1, acc1[rp]);   // col c+1, k+1
            }
        }
    }

#pragma unroll
    for (int rp = 0; rp < R_PAIRS; ++rp) {
        float lo0, hi0, lo1, hi1;
        asm("mov.b64 {%0, %1}, %2;" : "=f"(lo0), "=f"(hi0) : "l"(acc0[rp]));
        asm("mov.b64 {%0, %1}, %2;" : "=f"(lo1), "=f"(hi1) : "l"(acc1[rp]));
        const int s0 = s_idx[2 * rp];
        const int s1 = s_idx[2 * rp + 1];
        if (s0 >= 0)
            *reinterpret_cast<float2*>(&out[s0 * OUT_F + c]) =
                make_float2(lo0 + bv.x, lo1 + bv.y);
        if (s1 >= 0)
            *reinterpret_cast<float2*>(&out[s1 * OUT_F + c]) =
                make_float2(hi0 + bv.x, hi1 + bv.y);
    }
}

// ---------------------------------------------------------------------------
// Fused grouped kernel: one block per (combo, 256-col tile). Block = 128
// threads; thread t owns columns (tile*256 + 2t, +1). R_TILE=16 rows/chunk
// with a half path for <=8 live rows. Writes out = x@(W+0.1*DW) + bias
// directly — every (sample, col) is owned by exactly one block.
// ---------------------------------------------------------------------------
__global__ void __launch_bounds__(128)
fused_mm_kernel(const float* __restrict__ X,
                const float* __restrict__ W,
                const float* __restrict__ DW,
                const float* __restrict__ bias,
                float* __restrict__ out) {
    constexpr int R_TILE  = 16;
    constexpr int R_PAIRS = R_TILE / 2;

    const int g     = blockIdx.x;          // combo
    const int start = g_cstart[g];
    const int end   = g_cstart[g + 1];
    if (start >= end) return;

    const int head = g / N_SPLITS;
    const int t    = threadIdx.x;
    const int c    = blockIdx.y * 256 + 2 * t;

    const float* __restrict__ Wc = W  + (size_t)head * (IN_F * OUT_F) + c;
    const float* __restrict__ Dc = DW + (size_t)g    * (IN_F * OUT_F) + c;
    const float2 bv = *reinterpret_cast<const float2*>(&bias[head * OUT_F + c]);

    __shared__ float x_s[R_PAIRS * 2 * IN_F];   // 32 KB
    __shared__ int   s_idx[R_TILE];

    for (int r0 = start; r0 < end; r0 += R_TILE) {
        const int rows = min(R_TILE, end - r0);
        if (t < R_TILE) s_idx[t] = (t < rows) ? g_sorted[r0 + t] : -1;
        __syncthreads();

        const bool small = (rows <= R_TILE / 2);
        const int fill = (small ? R_PAIRS / 2 : R_PAIRS) * 2 * IN_F;

        for (int idx = t; idx < fill; idx += 128) {
            const int r = idx >> 9;            // idx / IN_F
            const int k = idx & (IN_F - 1);
            const int s = s_idx[r];
            x_s[(r >> 1) * (2 * IN_F) + 2 * k + (r & 1)] =
                (s >= 0) ? X[s * IN_F + k] : 0.0f;
        }
        __syncthreads();

        if (small)
            compute_rows<R_PAIRS / 2>(Wc, Dc, x_s, s_idx, bv, out, c);
        else
            compute_rows<R_PAIRS>(Wc, Dc, x_s, s_idx, bv, out, c);
        __syncthreads();   // protect x_s / s_idx before next chunk
    }
}

// ---------------------------------------------------------------------------
// kernel_launch: inputs in metadata order
//   0 input f32[1024,512]  1 head_ix i32[1024]  2 split_ix i32[1024]
//   3 weight f32[32,512,512]  4 delta_weight f32[128,512,512]  5 bias f32[32,512]
// ---------------------------------------------------------------------------
extern "C" void kernel_launch(void* const* d_in, const int* in_sizes, int n_in,
                              void* d_out, int out_size) {
    const float* X    = (const float*)d_in[0];
    const int*   hix  = (const int*)d_in[1];
    const int*   six  = (const int*)d_in[2];
    const float* W    = (const float*)d_in[3];
    const float* DW   = (const float*)d_in[4];
    const float* bias = (const float*)d_in[5];

    // Defensive size-based resolution for uniquely-sized inputs.
    for (int i = 0; i < n_in; ++i) {
        switch (in_sizes[i]) {
            case N_SAMPLES * IN_F:        X    = (const float*)d_in[i]; break;
            case N_HEADS * IN_F * OUT_F:  W    = (const float*)d_in[i]; break;
            case N_COMBOS * IN_F * OUT_F: DW   = (const float*)d_in[i]; break;
            case N_HEADS * OUT_F:         bias = (const float*)d_in[i]; break;
            default: break; // head_ix / split_ix keep metadata positions
        }
    }

    float* out = (float*)d_out;

    setup_groups_kernel<<<1, N_SAMPLES>>>(hix, six);

    // 128 combos x 2 col tiles = 256 blocks of 128 threads, single fused pass.
    fused_mm_kernel<<<dim3(N_COMBOS, OUT_F / 256), 128>>>(X, W, DW, bias, out);
}

// round 9
// speedup vs baseline: 3.7857x; 2.1989x over previous
#include <cuda_runtime.h>
#include <cstdint>
#include <cstddef>

#define N_SAMPLES 1024
#define IN_F      512
#define OUT_F     512
#define N_HEADS   32
#define N_SPLITS  4
#define N_COMBOS  (N_HEADS * N_SPLITS)
#define DELTA_SCALE 0.1f
#define K_SLICES  4
#define K_SLICE   (IN_F / K_SLICES)      // 128

// ---------------------------------------------------------------------------
// Device scratch (no cudaMalloc allowed anywhere)
// ---------------------------------------------------------------------------
__device__ int   g_sorted[N_SAMPLES];                    // sample ids by combo
__device__ int   g_cstart[N_COMBOS + 1];                 // combo -> range
__device__ float g_partial[K_SLICES][N_SAMPLES * OUT_F]; // 8 MB k-slice partials

// ---------------------------------------------------------------------------
// Grouping kernel: counting sort by combo = head*4 + split.
// One block, 1024 threads (1 sample/thread), warp-shuffle scan.
// ---------------------------------------------------------------------------
__global__ void __launch_bounds__(N_SAMPLES)
setup_groups_kernel(const int* __restrict__ head_ix,
                    const int* __restrict__ split_ix) {
    __shared__ int cnt[N_COMBOS];
    __shared__ int cur[N_COMBOS];
    const int t = threadIdx.x;

    if (t < N_COMBOS) cnt[t] = 0;
    __syncthreads();

    const int my_c = head_ix[t] * N_SPLITS + split_ix[t];
    atomicAdd(&cnt[my_c], 1);
    __syncthreads();

    if (t < 32) {
        int c0 = cnt[4 * t + 0], c1 = cnt[4 * t + 1];
        int c2 = cnt[4 * t + 2], c3 = cnt[4 * t + 3];
        int v = c0 + c1 + c2 + c3;
        int s = v;
#pragma unroll
        for (int d = 1; d < 32; d <<= 1) {
            int u = __shfl_up_sync(0xFFFFFFFFu, s, d);
            if (t >= d) s += u;
        }
        int run = s - v;                       // exclusive prefix
        if (t == 0) g_cstart[0] = 0;
        run += c0; g_cstart[4 * t + 1] = run; cur[4 * t + 0] = run - c0;
        run += c1; g_cstart[4 * t + 2] = run; cur[4 * t + 1] = run - c1;
        run += c2; g_cstart[4 * t + 3] = run; cur[4 * t + 2] = run - c2;
        run += c3; g_cstart[4 * t + 4] = run; cur[4 * t + 3] = run - c3;
    }
    __syncthreads();

    g_sorted[atomicAdd(&cur[my_c], 1)] = t;
}

// ---------------------------------------------------------------------------
// Packed-pair fp32x2 FMA (SASS FFMA2 — only reachable via PTX fma.rn.f32x2)
// ---------------------------------------------------------------------------
#define FMA2(d, a, b, c) \
    asm("fma.rn.f32x2 %0, %1, %2, %3;" : "=l"(d) : "l"(a), "l"(b), "l"(c))
#define PACK2(d, s) \
    asm("mov.b64 %0, {%1, %1};" : "=l"(d) : "f"(s))

// ---------------------------------------------------------------------------
// Per-slice compute: thread owns 2 adjacent columns (c, c+1); accumulates
// R_PAIRS row-pairs over 128 local k with a 4k-ahead float2 prefetch of W/DW.
// Weights are combined on the fly: w' = W + 0.1*DW (one scalar FFMA each).
// x_s layout: pair rp, local k -> { x[2rp][k], x[2rp+1][k] } interleaved so a
// single LDS.128 yields two packed b64 FFMA2 operands (broadcast, no conflict).
// Result (no bias) is written to this slice's partial buffer.
// ---------------------------------------------------------------------------
template <int R_PAIRS>
__device__ __forceinline__ void compute_slice(const float* __restrict__ Wc,
                                              const float* __restrict__ Dc,
                                              const float* x_s,
                                              const int*   s_idx,
                                              float* __restrict__ partial,
                                              int c) {
    unsigned long long acc0[R_PAIRS], acc1[R_PAIRS];   // col c / col c+1
#pragma unroll
    for (int rp = 0; rp < R_PAIRS; ++rp) { acc0[rp] = 0ull; acc1[rp] = 0ull; }

    float2 wb[2][4], db[2][4];
#pragma unroll
    for (int j = 0; j < 4; ++j) {
        wb[0][j] = *reinterpret_cast<const float2*>(Wc + (size_t)j * OUT_F);
        db[0][j] = *reinterpret_cast<const float2*>(Dc + (size_t)j * OUT_F);
    }

#pragma unroll 2
    for (int kb = 0; kb < K_SLICE; kb += 4) {
        const int cur = (kb >> 2) & 1;
        const int nxt = cur ^ 1;
        const int kp  = (kb + 4) & (K_SLICE - 1);   // wraps last iter (unused)
#pragma unroll
        for (int j = 0; j < 4; ++j) {
            wb[nxt][j] = *reinterpret_cast<const float2*>(Wc + (size_t)(kp + j) * OUT_F);
            db[nxt][j] = *reinterpret_cast<const float2*>(Dc + (size_t)(kp + j) * OUT_F);
        }

#pragma unroll
        for (int j = 0; j < 4; j += 2) {            // k-pair (kb+j, kb+j+1)
            const float wa0 = fmaf(DELTA_SCALE, db[cur][j].x,     wb[cur][j].x);
            const float wa1 = fmaf(DELTA_SCALE, db[cur][j].y,     wb[cur][j].y);
            const float wb0 = fmaf(DELTA_SCALE, db[cur][j + 1].x, wb[cur][j + 1].x);
            const float wb1 = fmaf(DELTA_SCALE, db[cur][j + 1].y, wb[cur][j + 1].y);
            unsigned long long a0, a1, b0, b1;
            PACK2(a0, wa0); PACK2(a1, wa1); PACK2(b0, wb0); PACK2(b1, wb1);
#pragma unroll
            for (int rp = 0; rp < R_PAIRS; ++rp) {
                const ulonglong2 xv = *reinterpret_cast<const ulonglong2*>(
                    &x_s[rp * (2 * K_SLICE) + 2 * (kb + j)]);
                FMA2(acc0[rp], xv.x, a0, acc0[rp]);
                FMA2(acc1[rp], xv.x, a1, acc1[rp]);
                FMA2(acc0[rp], xv.y, b0, acc0[rp]);
                FMA2(acc1[rp], xv.y, b1, acc1[rp]);
            }
        }
    }

#pragma unroll
    for (int rp = 0; rp < R_PAIRS; ++rp) {
        float lo0, hi0, lo1, hi1;
        asm("mov.b64 {%0, %1}, %2;" : "=f"(lo0), "=f"(hi0) : "l"(acc0[rp]));
        asm("mov.b64 {%0, %1}, %2;" : "=f"(lo1), "=f"(hi1) : "l"(acc1[rp]));
        const int s0 = s_idx[2 * rp];
        const int s1 = s_idx[2 * rp + 1];
        if (s0 >= 0)
            *reinterpret_cast<float2*>(&partial[s0 * OUT_F + c]) =
                make_float2(lo0, lo1);
        if (s1 >= 0)
            *reinterpret_cast<float2*>(&partial[s1 * OUT_F + c]) =
                make_float2(hi0, hi1);
    }
}

// ---------------------------------------------------------------------------
// Fused grouped kernel, k-split for occupancy.
//   Grid: (128 combos, 2 col-tiles of 256, 4 k-slices of 128); 128 threads,
//   thread t owns columns (tile*256 + 2t, +1). Each block streams its W/DW
//   [128k x 256c] slices once and writes partial sums for its k-slice.
//   Row paths: <=4, <=8, <=16 live rows to skip padded FMAs.
// ---------------------------------------------------------------------------
__global__ void __launch_bounds__(128, 5)
fused_mm_kernel(const float* __restrict__ X,
                const float* __restrict__ W,
                const float* __restrict__ DW) {
    constexpr int R_TILE = 16;

    const int g     = blockIdx.x;          // combo
    const int start = g_cstart[g];
    const int end   = g_cstart[g + 1];
    if (start >= end) return;

    const int head = g >> 2;
    const int t    = threadIdx.x;
    const int c    = blockIdx.y * 256 + 2 * t;
    const int z    = blockIdx.z;
    const int k0   = z * K_SLICE;

    const float* __restrict__ Wc = W  + (size_t)head * (IN_F * OUT_F) + (size_t)k0 * OUT_F + c;
    const float* __restrict__ Dc = DW + (size_t)g    * (IN_F * OUT_F) + (size_t)k0 * OUT_F + c;
    float* __restrict__ partial = g_partial[z];

    __shared__ float x_s[(R_TILE / 2) * 2 * K_SLICE];   // 8 KB
    __shared__ int   s_idx[R_TILE];

    for (int r0 = start; r0 < end; r0 += R_TILE) {
        const int rows = min(R_TILE, end - r0);
        if (t < R_TILE) s_idx[t] = (t < rows) ? g_sorted[r0 + t] : -1;
        __syncthreads();

        const int pairs = (rows <= 4) ? 2 : (rows <= 8) ? 4 : 8;
        const int fill  = pairs * 2 * K_SLICE;

        for (int idx = t; idx < fill; idx += 128) {
            const int r = idx >> 7;              // idx / K_SLICE
            const int k = idx & (K_SLICE - 1);
            const int s = s_idx[r];
            x_s[(r >> 1) * (2 * K_SLICE) + 2 * k + (r & 1)] =
                (s >= 0) ? X[s * IN_F + k0 + k] : 0.0f;
        }
        __syncthreads();

        if (pairs == 2)
            compute_slice<2>(Wc, Dc, x_s, s_idx, partial, c);
        else if (pairs == 4)
            compute_slice<4>(Wc, Dc, x_s, s_idx, partial, c);
        else
            compute_slice<8>(Wc, Dc, x_s, s_idx, partial, c);
        __syncthreads();   // protect x_s / s_idx before next chunk
    }
}

// ---------------------------------------------------------------------------
// Reduce kernel: out[s][c..c+3] = sum_z partial[z][s][c..c+3] + bias[head[s]].
// 131072 threads, float4 per thread.
// ---------------------------------------------------------------------------
__global__ void __launch_bounds__(256)
reduce_kernel(const int* __restrict__ head_ix,
              const float* __restrict__ bias,
              float* __restrict__ out) {
    const int idx = blockIdx.x * 256 + threadIdx.x;   // 0 .. 131071
    const int s   = idx >> 7;
    const int c   = (idx & 127) * 4;
    const size_t o = (size_t)s * OUT_F + c;

    const float4 p0 = *reinterpret_cast<const float4*>(&g_partial[0][o]);
    const float4 p1 = *reinterpret_cast<const float4*>(&g_partial[1][o]);
    const float4 p2 = *reinterpret_cast<const float4*>(&g_partial[2][o]);
    const float4 p3 = *reinterpret_cast<const float4*>(&g_partial[3][o]);
    const float4 bv = *reinterpret_cast<const float4*>(&bias[head_ix[s] * OUT_F + c]);

    float4 r;
    r.x = ((p0.x + p1.x) + (p2.x + p3.x)) + bv.x;
    r.y = ((p0.y + p1.y) + (p2.y + p3.y)) + bv.y;
    r.z = ((p0.z + p1.z) + (p2.z + p3.z)) + bv.z;
    r.w = ((p0.w + p1.w) + (p2.w + p3.w)) + bv.w;
    *reinterpret_cast<float4*>(&out[o]) = r;
}

// ---------------------------------------------------------------------------
// kernel_launch: inputs in metadata order
//   0 input f32[1024,512]  1 head_ix i32[1024]  2 split_ix i32[1024]
//   3 weight f32[32,512,512]  4 delta_weight f32[128,512,512]  5 bias f32[32,512]
// ---------------------------------------------------------------------------
extern "C" void kernel_launch(void* const* d_in, const int* in_sizes, int n_in,
                              void* d_out, int out_size) {
    const float* X    = (const float*)d_in[0];
    const int*   hix  = (const int*)d_in[1];
    const int*   six  = (const int*)d_in[2];
    const float* W    = (const float*)d_in[3];
    const float* DW   = (const float*)d_in[4];
    const float* bias = (const float*)d_in[5];

    for (int i = 0; i < n_in; ++i) {
        switch (in_sizes[i]) {
            case N_SAMPLES * IN_F:        X    = (const float*)d_in[i]; break;
            case N_HEADS * IN_F * OUT_F:  W    = (const float*)d_in[i]; break;
            case N_COMBOS * IN_F * OUT_F: DW   = (const float*)d_in[i]; break;
            case N_HEADS * OUT_F:         bias = (const float*)d_in[i]; break;
            default: break; // head_ix / split_ix keep metadata positions
        }
    }

    float* out = (float*)d_out;

    setup_groups_kernel<<<1, N_SAMPLES>>>(hix, six);

    // 128 combos x 2 col-tiles x 4 k-slices = 1024 blocks of 128 threads.
    fused_mm_kernel<<<dim3(N_COMBOS, OUT_F / 256, K_SLICES), 128>>>(X, W, DW);

    // Sum the 4 k-slice partials + per-head bias into d_out.
    reduce_kernel<<<(N_SAMPLES * OUT_F / 4) / 256, 256>>>(hix, bias, out);
}

// round 15
// speedup vs baseline: 3.9421x; 1.0413x over previous
#include <cuda_runtime.h>
#include <cstdint>
#include <cstddef>

#define N_SAMPLES 1024
#define IN_F      512
#define OUT_F     512
#define N_HEADS   32
#define N_SPLITS  4
#define N_COMBOS  (N_HEADS * N_SPLITS)
#define DELTA_SCALE 0.1f
#define K_SLICES  4
#define K_SLICE   (IN_F / K_SLICES)      // 128

// ---------------------------------------------------------------------------
// Device scratch (no cudaMalloc allowed anywhere)
// ---------------------------------------------------------------------------
__device__ float g_partial[K_SLICES][N_SAMPLES * OUT_F]; // 8 MB k-slice partials

// ---------------------------------------------------------------------------
// Packed-pair fp32x2 FMA (SASS FFMA2 — only reachable via PTX fma.rn.f32x2)
// ---------------------------------------------------------------------------
#define FMA2(d, a, b, c) \
    asm("fma.rn.f32x2 %0, %1, %2, %3;" : "=l"(d) : "l"(a), "l"(b), "l"(c))
#define PACK2(d, s) \
    asm("mov.b64 %0, {%1, %1};" : "=l"(d) : "f"(s))

// ---------------------------------------------------------------------------
// Per-slice compute: thread owns 2 adjacent columns (c, c+1); accumulates
// R_PAIRS row-pairs over 128 local k with a 4k-ahead float2 prefetch of W/DW.
// Weights combined on the fly: w' = W + 0.1*DW (one scalar FFMA each).
// x_s layout: pair rp, local k -> { x[2rp][k], x[2rp+1][k] } interleaved so a
// single LDS.128 yields two packed b64 FFMA2 operands (broadcast, no conflict).
// NOTE: x_s MUST be 16-byte aligned — accessed via ulonglong2 (LDS.128).
// ---------------------------------------------------------------------------
template <int R_PAIRS>
__device__ __forceinline__ void compute_slice(const float* __restrict__ Wc,
                                              const float* __restrict__ Dc,
                                              const float* x_s,
                                              const int*   s_idx,
                                              float* __restrict__ partial,
                                              int c) {
    unsigned long long acc0[R_PAIRS], acc1[R_PAIRS];   // col c / col c+1
#pragma unroll
    for (int rp = 0; rp < R_PAIRS; ++rp) { acc0[rp] = 0ull; acc1[rp] = 0ull; }

    float2 wb[2][4], db[2][4];
#pragma unroll
    for (int j = 0; j < 4; ++j) {
        wb[0][j] = *reinterpret_cast<const float2*>(Wc + (size_t)j * OUT_F);
        db[0][j] = *reinterpret_cast<const float2*>(Dc + (size_t)j * OUT_F);
    }

#pragma unroll 2
    for (int kb = 0; kb < K_SLICE; kb += 4) {
        const int cur = (kb >> 2) & 1;
        const int nxt = cur ^ 1;
        const int kp  = (kb + 4) & (K_SLICE - 1);   // wraps last iter (unused)
#pragma unroll
        for (int j = 0; j < 4; ++j) {
            wb[nxt][j] = *reinterpret_cast<const float2*>(Wc + (size_t)(kp + j) * OUT_F);
            db[nxt][j] = *reinterpret_cast<const float2*>(Dc + (size_t)(kp + j) * OUT_F);
        }

#pragma unroll
        for (int j = 0; j < 4; j += 2) {            // k-pair (kb+j, kb+j+1)
            const float wa0 = fmaf(DELTA_SCALE, db[cur][j].x,     wb[cur][j].x);
            const float wa1 = fmaf(DELTA_SCALE, db[cur][j].y,     wb[cur][j].y);
            const float wb0 = fmaf(DELTA_SCALE, db[cur][j + 1].x, wb[cur][j + 1].x);
            const float wb1 = fmaf(DELTA_SCALE, db[cur][j + 1].y, wb[cur][j + 1].y);
            unsigned long long a0, a1, b0, b1;
            PACK2(a0, wa0); PACK2(a1, wa1); PACK2(b0, wb0); PACK2(b1, wb1);
#pragma unroll
            for (int rp = 0; rp < R_PAIRS; ++rp) {
                const ulonglong2 xv = *reinterpret_cast<const ulonglong2*>(
                    &x_s[rp * (2 * K_SLICE) + 2 * (kb + j)]);
                FMA2(acc0[rp], xv.x, a0, acc0[rp]);
                FMA2(acc1[rp], xv.x, a1, acc1[rp]);
                FMA2(acc0[rp], xv.y, b0, acc0[rp]);
                FMA2(acc1[rp], xv.y, b1, acc1[rp]);
            }
        }
    }

#pragma unroll
    for (int rp = 0; rp < R_PAIRS; ++rp) {
        float lo0, hi0, lo1, hi1;
        asm("mov.b64 {%0, %1}, %2;" : "=f"(lo0), "=f"(hi0) : "l"(acc0[rp]));
        asm("mov.b64 {%0, %1}, %2;" : "=f"(lo1), "=f"(hi1) : "l"(acc1[rp]));
        const int s0 = s_idx[2 * rp];
        const int s1 = s_idx[2 * rp + 1];
        if (s0 >= 0)
            *reinterpret_cast<float2*>(&partial[s0 * OUT_F + c]) =
                make_float2(lo0, lo1);
        if (s1 >= 0)
            *reinterpret_cast<float2*>(&partial[s1 * OUT_F + c]) =
                make_float2(hi0, hi1);
    }
}

// ---------------------------------------------------------------------------
// Fused grouped kernel, k-split for occupancy, SELF-GROUPING (no setup pass).
//   Grid: (128 combos, 2 col-tiles of 256, 4 k-slices of 128); 128 threads.
//   Prologue: warp-ballot ordered compaction of the 1024 samples matching
//   this block's combo into smem (deterministic: sample-index order).
//   Mainloop: stream W/DW [128k x 256c] once, FFMA2 over row-pairs, write
//   k-slice partials. Row paths: <=4, <=8, <=16 live rows per chunk.
// ---------------------------------------------------------------------------
__global__ void __launch_bounds__(128, 5)
fused_mm_kernel(const float* __restrict__ X,
                const float* __restrict__ W,
                const float* __restrict__ DW,
                const int* __restrict__ head_ix,
                const int* __restrict__ split_ix) {
    constexpr int R_TILE = 16;

    const int g = blockIdx.x;              // combo
    const int t = threadIdx.x;
    const int lane = t & 31;
    const int w    = t >> 5;               // warp id (0..3), owns samples [w*256, +256)

    // x_s FIRST and explicitly 16B-aligned: it is read with LDS.128
    // (ulonglong2). R10 crashed (misaligned address) because a 20-byte smem
    // array declared before it shifted x_s off 16B alignment.
    __shared__ __align__(16) float x_s[(R_TILE / 2) * 2 * K_SLICE];   // 8 KB
    __shared__ int   s_list[N_SAMPLES];    // 4 KB: this combo's samples, ordered
    __shared__ int   s_idx[R_TILE];
    __shared__ int   wcnt[4];
    __shared__ int   woff[8];              // 5 used; padded

    // ---- ordered compaction of samples with combo == g ----
    bool hit[8];
#pragma unroll
    for (int r = 0; r < 8; ++r) {
        const int s = (w << 8) + (r << 5) + lane;
        hit[r] = (head_ix[s] * N_SPLITS + split_ix[s] == g);
    }
    unsigned masks[8];
    int mycnt = 0;
#pragma unroll
    for (int r = 0; r < 8; ++r) {
        masks[r] = __ballot_sync(0xFFFFFFFFu, hit[r]);
        mycnt += __popc(masks[r]);
    }
    if (lane == 0) wcnt[w] = mycnt;
    __syncthreads();
    if (t == 0) {
        int s = 0;
#pragma unroll
        for (int i = 0; i < 4; ++i) { woff[i] = s; s += wcnt[i]; }
        woff[4] = s;
    }
    __syncthreads();
    {
        int off = woff[w];
#pragma unroll
        for (int r = 0; r < 8; ++r) {
            if (hit[r]) {
                const int pos = off + __popc(masks[r] & ((1u << lane) - 1u));
                s_list[pos] = (w << 8) + (r << 5) + lane;
            }
            off += __popc(masks[r]);
        }
    }
    __syncthreads();
    const int count = woff[4];
    if (count == 0) return;

    // ---- mainloop ----
    const int head = g >> 2;
    const int c    = blockIdx.y * 256 + 2 * t;
    const int k0   = blockIdx.z * K_SLICE;

    const float* __restrict__ Wc = W  + (size_t)head * (IN_F * OUT_F) + (size_t)k0 * OUT_F + c;
    const float* __restrict__ Dc = DW + (size_t)g    * (IN_F * OUT_F) + (size_t)k0 * OUT_F + c;
    float* __restrict__ partial = g_partial[blockIdx.z];

    for (int r0 = 0; r0 < count; r0 += R_TILE) {
        const int rows = min(R_TILE, count - r0);
        if (t < R_TILE) s_idx[t] = (t < rows) ? s_list[r0 + t] : -1;
        __syncthreads();

        const int pairs = (rows <= 4) ? 2 : (rows <= 8) ? 4 : 8;
        const int fill  = pairs * 2 * K_SLICE;

        for (int idx = t; idx < fill; idx += 128) {
            const int r = idx >> 7;              // idx / K_SLICE
            const int k = idx & (K_SLICE - 1);
            const int s = s_idx[r];
            x_s[(r >> 1) * (2 * K_SLICE) + 2 * k + (r & 1)] =
                (s >= 0) ? X[s * IN_F + k0 + k] : 0.0f;
        }
        __syncthreads();

        if (pairs == 2)
            compute_slice<2>(Wc, Dc, x_s, s_idx, partial, c);
        else if (pairs == 4)
            compute_slice<4>(Wc, Dc, x_s, s_idx, partial, c);
        else
            compute_slice<8>(Wc, Dc, x_s, s_idx, partial, c);
        __syncthreads();   // protect x_s / s_idx before next chunk
    }
}

// ---------------------------------------------------------------------------
// Reduce kernel: out[s][c..c+3] = sum_z partial[z][s][c..c+3] + bias[head[s]].
// 131072 threads, float4 per thread.
// ---------------------------------------------------------------------------
__global__ void __launch_bounds__(256)
reduce_kernel(const int* __restrict__ head_ix,
              const float* __restrict__ bias,
              float* __restrict__ out) {
    const int idx = blockIdx.x * 256 + threadIdx.x;   // 0 .. 131071
    const int s   = idx >> 7;
    const int c   = (idx & 127) * 4;
    const size_t o = (size_t)s * OUT_F + c;

    const float4 p0 = *reinterpret_cast<const float4*>(&g_partial[0][o]);
    const float4 p1 = *reinterpret_cast<const float4*>(&g_partial[1][o]);
    const float4 p2 = *reinterpret_cast<const float4*>(&g_partial[2][o]);
    const float4 p3 = *reinterpret_cast<const float4*>(&g_partial[3][o]);
    const float4 bv = *reinterpret_cast<const float4*>(&bias[head_ix[s] * OUT_F + c]);

    float4 r;
    r.x = ((p0.x + p1.x) + (p2.x + p3.x)) + bv.x;
    r.y = ((p0.y + p1.y) + (p2.y + p3.y)) + bv.y;
    r.z = ((p0.z + p1.z) + (p2.z + p3.z)) + bv.z;
    r.w = ((p0.w + p1.w) + (p2.w + p3.w)) + bv.w;
    *reinterpret_cast<float4*>(&out[o]) = r;
}

// ---------------------------------------------------------------------------
// kernel_launch: inputs in metadata order
//   0 input f32[1024,512]  1 head_ix i32[1024]  2 split_ix i32[1024]
//   3 weight f32[32,512,512]  4 delta_weight f32[128,512,512]  5 bias f32[32,512]
// ---------------------------------------------------------------------------
extern "C" void kernel_launch(void* const* d_in, const int* in_sizes, int n_in,
                              void* d_out, int out_size) {
    const float* X    = (const float*)d_in[0];
    const int*   hix  = (const int*)d_in[1];
    const int*   six  = (const int*)d_in[2];
    const float* W    = (const float*)d_in[3];
    const float* DW   = (const float*)d_in[4];
    const float* bias = (const float*)d_in[5];

    for (int i = 0; i < n_in; ++i) {
        switch (in_sizes[i]) {
            case N_SAMPLES * IN_F:        X    = (const float*)d_in[i]; break;
            case N_HEADS * IN_F * OUT_F:  W    = (const float*)d_in[i]; break;
            case N_COMBOS * IN_F * OUT_F: DW   = (const float*)d_in[i]; break;
            case N_HEADS * OUT_F:         bias = (const float*)d_in[i]; break;
            default: break; // head_ix / split_ix keep metadata positions
        }
    }

    float* out = (float*)d_out;

    // Single fused pass: 128 combos x 2 col-tiles x 4 k-slices = 1024 blocks.
    fused_mm_kernel<<<dim3(N_COMBOS, OUT_F / 256, K_SLICES), 128>>>(
        X, W, DW, hix, six);

    // Sum the 4 k-slice partials + per-head bias into d_out.
    reduce_kernel<<<(N_SAMPLES * OUT_F / 4) / 256, 256>>>(hix, bias, out);
}